// round 2
// baseline (speedup 1.0000x reference)
#include <cuda_runtime.h>
#include <cuda_bf16.h>
#include <math_constants.h>
#include <cfloat>

// Problem: REAFT loss over logits [B, S, V] fp32, labels [B, S] int32
// (JAX x64 disabled -> int64 request yields int32), attention_mask [B, S]
// int32 -> scalar fp32.  B=2, S=2048, V=32000.

#define SHOCK_THRESHOLD 5.0f
#define ALPHA 3.0f
#define LOSS_EPS 1e-6f

#define MAX_ROWS 8192

// Per-row scratch (static device arrays: allocation-free, rewritten every launch)
__device__ float g_row_w[MAX_ROWS];
__device__ int   g_row_v[MAX_ROWS];

// Combine two online-softmax triples (m, s, t):
//   s = sum exp(x - m), t = sum x*exp(x - m)
__device__ __forceinline__ void combine_mst(float& m, float& s, float& t,
                                            float m2, float s2, float t2) {
    float mn = fmaxf(m, m2);
    float a  = __expf(m  - mn);   // 1 if m == mn; underflows to 0 for -FLT_MAX
    float b  = __expf(m2 - mn);
    s = s * a + s2 * b;
    t = t * a + t2 * b;
    m = mn;
}

__global__ void __launch_bounds__(256, 8)
reaft_row_kernel(const float* __restrict__ logits,
                 const int* __restrict__ labels,
                 const int* __restrict__ amask,
                 int S, int V) {
    const int r   = blockIdx.x;          // row in shifted space: 0 .. B*(S-1)-1
    const int rpb = S - 1;               // rows per batch
    const int b   = r / rpb;
    const int q   = r - b * rpb;         // 0 .. S-2

    const float* __restrict__ row = logits + (size_t)(b * S + q) * (size_t)V;

    // ---- online (m, s, t) over the row, float4 chunks ----
    float m = -FLT_MAX, s = 0.f, t = 0.f;

    const int nvec = V >> 2;
    const float4* __restrict__ rv = (const float4*)row;

    for (int i = threadIdx.x; i < nvec; i += blockDim.x) {
        float4 v = rv[i];
        float cm = fmaxf(fmaxf(v.x, v.y), fmaxf(v.z, v.w));
        float mn = fmaxf(m, cm);
        float sc = __expf(m - mn);       // rescale old accumulators
        float e0 = __expf(v.x - mn);
        float e1 = __expf(v.y - mn);
        float e2 = __expf(v.z - mn);
        float e3 = __expf(v.w - mn);
        s = s * sc + ((e0 + e1) + (e2 + e3));
        t = t * sc + ((v.x * e0 + v.y * e1) + (v.z * e2 + v.w * e3));
        m = mn;
    }
    // scalar tail (V % 4) — none for V=32000, kept for generality
    for (int i = (nvec << 2) + threadIdx.x; i < V; i += blockDim.x) {
        float x  = row[i];
        float mn = fmaxf(m, x);
        float sc = __expf(m - mn);
        float e  = __expf(x - mn);
        s = s * sc + e;
        t = t * sc + x * e;
        m = mn;
    }

    // ---- warp reduce ----
    #pragma unroll
    for (int off = 16; off > 0; off >>= 1) {
        float m2 = __shfl_down_sync(0xFFFFFFFFu, m, off);
        float s2 = __shfl_down_sync(0xFFFFFFFFu, s, off);
        float t2 = __shfl_down_sync(0xFFFFFFFFu, t, off);
        combine_mst(m, s, t, m2, s2, t2);
    }

    // ---- cross-warp reduce via smem ----
    __shared__ float sm[8], ss[8], st[8];
    const int wid = threadIdx.x >> 5;
    const int lid = threadIdx.x & 31;
    if (lid == 0) { sm[wid] = m; ss[wid] = s; st[wid] = t; }
    __syncthreads();

    if (wid == 0) {
        const int nw = blockDim.x >> 5;   // 8
        if (lid < nw) { m = sm[lid]; s = ss[lid]; t = st[lid]; }
        else          { m = -FLT_MAX; s = 0.f; t = 0.f; }
        #pragma unroll
        for (int off = 4; off > 0; off >>= 1) {
            float m2 = __shfl_down_sync(0xFFFFFFFFu, m, off);
            float s2 = __shfl_down_sync(0xFFFFFFFFu, s, off);
            float t2 = __shfl_down_sync(0xFFFFFFFFu, t, off);
            combine_mst(m, s, t, m2, s2, t2);
        }
        if (lid == 0) {
            // shifted label / mask come from position q+1
            int lab = labels[b * S + q + 1];
            int msk = amask[b * S + q + 1];

            float lse     = m + logf(s);
            float entropy = lse - t / s;          // lse - E_p[x]

            float tl = 0.f;
            if (lab != -100) {
                // clamp index for the load only (defensive; raw lab drives validity)
                int li = lab < 0 ? 0 : (lab >= V ? V - 1 : lab);
                float xl = row[li];
                tl = lse - xl;                    // -log_softmax at label
            }
            float ne  = entropy / logf((float)V);
            float sr  = tl / (ne + LOSS_EPS);
            float sf  = fminf(sr * (1.0f / SHOCK_THRESHOLD), 10.0f);
            float w   = (sr > SHOCK_THRESHOLD) ? (1.0f + ALPHA * sf) : ne;
            int valid = (lab != -100) && (msk != 0);

            g_row_w[r] = valid ? (tl * w) : 0.f;
            g_row_v[r] = valid;
        }
    }
}

__global__ void __launch_bounds__(1024)
reaft_finalize_kernel(float* __restrict__ out, int R) {
    float ws = 0.f;
    int   vc = 0;
    for (int i = threadIdx.x; i < R; i += blockDim.x) {
        ws += g_row_w[i];
        vc += g_row_v[i];
    }
    // warp reduce
    #pragma unroll
    for (int off = 16; off > 0; off >>= 1) {
        ws += __shfl_down_sync(0xFFFFFFFFu, ws, off);
        vc += __shfl_down_sync(0xFFFFFFFFu, vc, off);
    }
    __shared__ float sw[32];
    __shared__ int   sv[32];
    const int wid = threadIdx.x >> 5;
    const int lid = threadIdx.x & 31;
    if (lid == 0) { sw[wid] = ws; sv[wid] = vc; }
    __syncthreads();
    if (wid == 0) {
        const int nw = blockDim.x >> 5;  // 32
        ws = (lid < nw) ? sw[lid] : 0.f;
        vc = (lid < nw) ? sv[lid] : 0;
        #pragma unroll
        for (int off = 16; off > 0; off >>= 1) {
            ws += __shfl_down_sync(0xFFFFFFFFu, ws, off);
            vc += __shfl_down_sync(0xFFFFFFFFu, vc, off);
        }
        if (lid == 0) {
            float denom = (float)(vc > 1 ? vc : 1);
            out[0] = ws / denom;
        }
    }
}

extern "C" void kernel_launch(void* const* d_in, const int* in_sizes, int n_in,
                              void* d_out, int out_size) {
    const float* logits = (const float*)d_in[0];
    const int*   labels = (const int*)d_in[1];
    const int*   amask  = (const int*)d_in[2];
    float*       out    = (float*)d_out;

    const int BS = in_sizes[1];          // B * S = 4096
    const int V  = in_sizes[0] / BS;     // 32000
    const int S  = 2048;                 // known problem shape
    const int B  = BS / S;
    const int R  = B * (S - 1);          // 4094 shifted rows

    reaft_row_kernel<<<R, 256>>>(logits, labels, amask, S, V);
    reaft_finalize_kernel<<<1, 1024>>>(out, R);
}